// round 7
// baseline (speedup 1.0000x reference)
#include <cuda_runtime.h>
#include <cstdint>

#define NN 50000
#define NE 1600000
#define DD 64
#define RR 4
#define LL 4
#define NB 256
#define NEG_SLOPE 0.2f

// ---------------- device scratch (static, allocation-free, 16B-aligned) ----------------
__device__ __align__(16) float    g_hbuf0[NN * DD];
__device__ __align__(16) float    g_hbuf1[NN * DD];
__device__ __align__(16) float    g_hr[NN * RR * DD];     // 51.2 MB, L2-resident
__device__ __align__(16) float    g_agg[NN * DD];         // reused as z for GAT
__device__ __align__(16) float    g_el[NN];
__device__ __align__(16) float    g_er[NN];
__device__ __align__(16) unsigned g_menc[NN];             // order-preserving float-max enc
__device__ __align__(16) float    g_den[NN];
__device__ __align__(16) float    g_ex[NE];
__device__ __align__(16) float    g_hg[NN * DD];

// ---------------- helpers ----------------
__device__ __forceinline__ const float* layer_in(int l, const float* h0) {
    if (l == 0) return h0;
    return ((l - 1) & 1) ? g_hbuf1 : g_hbuf0;
}
__device__ __forceinline__ float* layer_out(int l) {
    return (l & 1) ? g_hbuf1 : g_hbuf0;
}
__device__ __forceinline__ unsigned fenc(float f) {
    unsigned u = __float_as_uint(f);
    return (u & 0x80000000u) ? ~u : (u | 0x80000000u);
}
__device__ __forceinline__ float fdec(unsigned k) {
    return (k & 0x80000000u) ? __uint_as_float(k & 0x7FFFFFFFu)
                             : __uint_as_float(~k);
}
__device__ __forceinline__ void red_add_v4(float* addr, float x, float y, float z, float w) {
    asm volatile("red.global.add.v4.f32 [%0], {%1,%2,%3,%4};"
                 :: "l"(addr), "f"(x), "f"(y), "f"(z), "f"(w) : "memory");
}

// ---------------- hr = h @ Wrel[l] (all 4 relations); also zeroes agg row ----------------
__global__ void __launch_bounds__(128) k_hr(const float* __restrict__ h0, int l,
                                            const float* __restrict__ Wl) {
    extern __shared__ float sm[];
    float* Ws = sm;                       // RR*DD*DD = 16384 floats
    float* Hs = sm + RR * DD * DD;        // 128 * 65 floats (padded)
    const float* h = layer_in(l, h0);
    int tid = threadIdx.x;
    for (int i = tid; i < RR * DD * DD; i += 128) Ws[i] = Wl[i];
    int base = blockIdx.x * 128;
    for (int i = tid; i < 128 * DD; i += 128) {
        int row = i >> 6, col = i & 63;
        int n = base + row;
        Hs[row * 65 + col] = (n < NN) ? h[n * DD + col] : 0.f;
    }
    __syncthreads();
    int node = base + tid;
    if (node >= NN) return;

    // zero this node's agg row (runs before k_edge_agg)
    float4* az = (float4*)(g_agg + node * DD);
    float4 z4 = make_float4(0.f, 0.f, 0.f, 0.f);
#pragma unroll
    for (int q = 0; q < 16; q++) az[q] = z4;

    const float* hrow = Hs + tid * 65;
    float* outp = g_hr + (size_t)node * (RR * DD);
    for (int r = 0; r < RR; r++) {
        float acc[DD];
#pragma unroll
        for (int o = 0; o < DD; o++) acc[o] = 0.f;
        const float* Wr = Ws + r * DD * DD;
#pragma unroll 4
        for (int d = 0; d < DD; d++) {
            float hv = hrow[d];
            const float4* w4 = (const float4*)(Wr + d * DD);
#pragma unroll
            for (int q = 0; q < 16; q++) {
                float4 w = w4[q];
                acc[4 * q + 0] = fmaf(hv, w.x, acc[4 * q + 0]);
                acc[4 * q + 1] = fmaf(hv, w.y, acc[4 * q + 1]);
                acc[4 * q + 2] = fmaf(hv, w.z, acc[4 * q + 2]);
                acc[4 * q + 3] = fmaf(hv, w.w, acc[4 * q + 3]);
            }
        }
        float4* op = (float4*)(outp + r * DD);
#pragma unroll
        for (int q = 0; q < 16; q++)
            op[q] = make_float4(acc[4 * q], acc[4 * q + 1], acc[4 * q + 2], acc[4 * q + 3]);
    }
}

// ---------------- edge scatter: agg[dst] += hr[src, etype] ----------------
__global__ void __launch_bounds__(256) k_edge_agg(const int* __restrict__ src,
                                                  const int* __restrict__ dst,
                                                  const int* __restrict__ et) {
    int t = blockIdx.x * 256 + threadIdx.x;
    int e = t >> 4;
    if (e >= NE) return;
    int k = t & 15;
    int s = __ldg(src + e), d = __ldg(dst + e), r = __ldg(et + e);
    const float4 v = *(const float4*)(g_hr + (size_t)s * (RR * DD) + r * DD + k * 4);
    red_add_v4(g_agg + d * DD + k * 4, v.x, v.y, v.z, v.w);
}

// ---------------- node update: h' = relu(agg + h@Wloop + brel) ----------------
__global__ void __launch_bounds__(128) k_node(const float* __restrict__ h0, int l,
                                              const float* __restrict__ Wl,
                                              const float* __restrict__ br) {
    extern __shared__ float sm[];
    float* Ws = sm;                 // 4096
    float* Bs = sm + DD * DD;       // 64
    float* Hs = Bs + DD;            // 128*65
    const float* h = layer_in(l, h0);
    float* hout = layer_out(l);
    int tid = threadIdx.x;
    for (int i = tid; i < DD * DD; i += 128) Ws[i] = Wl[i];
    if (tid < DD) Bs[tid] = br[tid];
    int base = blockIdx.x * 128;
    for (int i = tid; i < 128 * DD; i += 128) {
        int row = i >> 6, col = i & 63;
        int n = base + row;
        Hs[row * 65 + col] = (n < NN) ? h[n * DD + col] : 0.f;
    }
    __syncthreads();
    int node = base + tid;
    if (node >= NN) return;
    const float* hrow = Hs + tid * 65;
    float acc[DD];
    const float4* ag = (const float4*)(g_agg + node * DD);
#pragma unroll
    for (int q = 0; q < 16; q++) {
        float4 a = ag[q];
        acc[4 * q + 0] = a.x + Bs[4 * q + 0];
        acc[4 * q + 1] = a.y + Bs[4 * q + 1];
        acc[4 * q + 2] = a.z + Bs[4 * q + 2];
        acc[4 * q + 3] = a.w + Bs[4 * q + 3];
    }
#pragma unroll 4
    for (int d = 0; d < DD; d++) {
        float hv = hrow[d];
        const float4* w4 = (const float4*)(Ws + d * DD);
#pragma unroll
        for (int q = 0; q < 16; q++) {
            float4 w = w4[q];
            acc[4 * q + 0] = fmaf(hv, w.x, acc[4 * q + 0]);
            acc[4 * q + 1] = fmaf(hv, w.y, acc[4 * q + 1]);
            acc[4 * q + 2] = fmaf(hv, w.z, acc[4 * q + 2]);
            acc[4 * q + 3] = fmaf(hv, w.w, acc[4 * q + 3]);
        }
    }
    float4* op = (float4*)(hout + node * DD);
#pragma unroll
    for (int q = 0; q < 16; q++)
        op[q] = make_float4(fmaxf(acc[4 * q + 0], 0.f), fmaxf(acc[4 * q + 1], 0.f),
                            fmaxf(acc[4 * q + 2], 0.f), fmaxf(acc[4 * q + 3], 0.f));
}

// ---------------- GAT: z = h@Wg, el/er dots; also init hg, menc, den ----------------
__global__ void __launch_bounds__(128) k_gatz(const float* __restrict__ h0,
                                              const float* __restrict__ Wg,
                                              const float* __restrict__ al,
                                              const float* __restrict__ ar) {
    extern __shared__ float sm[];
    float* Ws = sm;                  // 4096
    float* Aa = sm + DD * DD;        // 64
    float* Ab = Aa + DD;             // 64
    float* Hs = Ab + DD;             // 128*65
    const float* h = layer_in(LL, h0);   // output of last RGCN layer
    int tid = threadIdx.x;
    for (int i = tid; i < DD * DD; i += 128) Ws[i] = Wg[i];
    if (tid < DD) Aa[tid] = al[tid];
    else if (tid < 2 * DD) Ab[tid - DD] = ar[tid - DD];
    int base = blockIdx.x * 128;
    for (int i = tid; i < 128 * DD; i += 128) {
        int row = i >> 6, col = i & 63;
        int n = base + row;
        Hs[row * 65 + col] = (n < NN) ? h[n * DD + col] : 0.f;
    }
    __syncthreads();
    int node = base + tid;
    if (node >= NN) return;

    // init per-node GAT state (runs before the edge passes)
    float4* hz = (float4*)(g_hg + node * DD);
    float4 z4 = make_float4(0.f, 0.f, 0.f, 0.f);
#pragma unroll
    for (int q = 0; q < 16; q++) hz[q] = z4;
    g_menc[node] = 0x007FFFFFu;          // enc(-inf)
    g_den[node] = 0.f;

    const float* hrow = Hs + tid * 65;
    float acc[DD];
#pragma unroll
    for (int o = 0; o < DD; o++) acc[o] = 0.f;
#pragma unroll 4
    for (int d = 0; d < DD; d++) {
        float hv = hrow[d];
        const float4* w4 = (const float4*)(Ws + d * DD);
#pragma unroll
        for (int q = 0; q < 16; q++) {
            float4 w = w4[q];
            acc[4 * q + 0] = fmaf(hv, w.x, acc[4 * q + 0]);
            acc[4 * q + 1] = fmaf(hv, w.y, acc[4 * q + 1]);
            acc[4 * q + 2] = fmaf(hv, w.z, acc[4 * q + 2]);
            acc[4 * q + 3] = fmaf(hv, w.w, acc[4 * q + 3]);
        }
    }
    float el_v = 0.f, er_v = 0.f;
#pragma unroll
    for (int o = 0; o < DD; o++) {
        el_v = fmaf(acc[o], Aa[o], el_v);
        er_v = fmaf(acc[o], Ab[o], er_v);
    }
    float4* zp = (float4*)(g_agg + node * DD);    // reuse g_agg as z
#pragma unroll
    for (int q = 0; q < 16; q++)
        zp[q] = make_float4(acc[4 * q], acc[4 * q + 1], acc[4 * q + 2], acc[4 * q + 3]);
    g_el[node] = el_v;
    g_er[node] = er_v;
}

// ---------------- GAT edge passes ----------------
__device__ __forceinline__ float edge_e(const int* src, const int* dst, int e,
                                        int& s, int& d) {
    s = __ldg(src + e); d = __ldg(dst + e);
    float ev = g_el[s] + g_er[d];
    return ev > 0.f ? ev : NEG_SLOPE * ev;
}

__global__ void __launch_bounds__(256) k_edge_max(const int* __restrict__ src,
                                                   const int* __restrict__ dst) {
    int e = blockIdx.x * 256 + threadIdx.x;
    if (e >= NE) return;
    int s, d;
    float ev = edge_e(src, dst, e, s, d);
    atomicMax(&g_menc[d], fenc(ev));
}

__global__ void __launch_bounds__(256) k_edge_exp(const int* __restrict__ src,
                                                   const int* __restrict__ dst) {
    int e = blockIdx.x * 256 + threadIdx.x;
    if (e >= NE) return;
    int s, d;
    float ev = edge_e(src, dst, e, s, d);
    float m = fdec(g_menc[d]);
    float ex = __expf(ev - m);
    g_ex[e] = ex;
    atomicAdd(&g_den[d], ex);
}

__global__ void __launch_bounds__(256) k_edge_hg(const int* __restrict__ src,
                                                  const int* __restrict__ dst) {
    int t = blockIdx.x * 256 + threadIdx.x;
    int e = t >> 4;
    if (e >= NE) return;
    int k = t & 15;
    int s = __ldg(src + e), d = __ldg(dst + e);
    float w = __fdividef(__ldg(&g_ex[e]), fmaxf(__ldg(&g_den[d]), 1e-9f));
    const float4 z = *(const float4*)(g_agg + s * DD + k * 4);
    red_add_v4(g_hg + d * DD + k * 4, w * z.x, w * z.y, w * z.z, w * z.w);
}

// ---------------- pooling + dense head ----------------
__global__ void k_out_init(const float* __restrict__ bd, float* __restrict__ out) {
    int t = threadIdx.x;
    if (t < NB) out[t] = bd[0];
}

__global__ void __launch_bounds__(256) k_pool(const float* __restrict__ Wd,
                                              const int* __restrict__ gids,
                                              float* __restrict__ out) {
    int warp = (blockIdx.x * 256 + threadIdx.x) >> 5;
    int lane = threadIdx.x & 31;
    if (warp >= NN) return;
    float w0 = __ldg(Wd + lane), w1 = __ldg(Wd + 32 + lane);
    float p = g_hg[warp * DD + lane] * w0 + g_hg[warp * DD + 32 + lane] * w1;
    p += __shfl_xor_sync(0xffffffffu, p, 16);
    p += __shfl_xor_sync(0xffffffffu, p, 8);
    p += __shfl_xor_sync(0xffffffffu, p, 4);
    p += __shfl_xor_sync(0xffffffffu, p, 2);
    p += __shfl_xor_sync(0xffffffffu, p, 1);
    if (lane == 0) atomicAdd(out + __ldg(gids + warp), p);
}

// ---------------- launcher ----------------
extern "C" void kernel_launch(void* const* d_in, const int* in_sizes, int n_in,
                              void* d_out, int out_size) {
    const float* h    = (const float*)d_in[0];
    const float* Wrel = (const float*)d_in[1];
    const float* Wloop= (const float*)d_in[2];
    const float* brel = (const float*)d_in[3];
    const float* Wg   = (const float*)d_in[4];
    const float* al   = (const float*)d_in[5];
    const float* ar   = (const float*)d_in[6];
    const float* Wd   = (const float*)d_in[7];
    const float* bd   = (const float*)d_in[8];
    const int*   src  = (const int*)d_in[9];
    const int*   dst  = (const int*)d_in[10];
    const int*   et   = (const int*)d_in[11];
    const int*   gids = (const int*)d_in[12];
    float* out = (float*)d_out;

    const int hr_smem = (RR * DD * DD + 128 * 65) * 4;            // 98816 B
    const int nu_smem = (DD * DD + DD + 128 * 65) * 4;            // 49920 B
    const int gz_smem = (DD * DD + 2 * DD + 128 * 65) * 4;        // 50176 B
    cudaFuncSetAttribute((const void*)k_hr,   cudaFuncAttributeMaxDynamicSharedMemorySize, hr_smem);
    cudaFuncSetAttribute((const void*)k_node, cudaFuncAttributeMaxDynamicSharedMemorySize, nu_smem);
    cudaFuncSetAttribute((const void*)k_gatz, cudaFuncAttributeMaxDynamicSharedMemorySize, gz_smem);

    const int nblk   = (NN + 127) / 128;                 // 391
    const int eblk16 = (NE * 16 + 255) / 256;            // 100000
    const int eblk   = (NE + 255) / 256;                 // 6250
    const int pblk   = (NN * 32 + 255) / 256;            // 6250

    for (int l = 0; l < LL; l++) {
        k_hr<<<nblk, 128, hr_smem>>>(h, l, Wrel + l * RR * DD * DD);
        k_edge_agg<<<eblk16, 256>>>(src, dst, et);
        k_node<<<nblk, 128, nu_smem>>>(h, l, Wloop + l * DD * DD, brel + l * DD);
    }
    k_gatz<<<nblk, 128, gz_smem>>>(h, Wg, al, ar);
    k_edge_max<<<eblk, 256>>>(src, dst);
    k_edge_exp<<<eblk, 256>>>(src, dst);
    k_edge_hg<<<eblk16, 256>>>(src, dst);
    k_out_init<<<1, NB>>>(bd, out);
    k_pool<<<pblk, 256>>>(Wd, gids, out);
}